// round 2
// baseline (speedup 1.0000x reference)
#include <cuda_runtime.h>
#include <math.h>

#define D 128
#define DD (D * D * D)
#define FULLMASK 0xFFFFFFFFu

__device__ __forceinline__ float4 ldg4(const float* __restrict__ p) {
    return __ldg(reinterpret_cast<const float4*>(p));
}

// Accumulate contact forces from one particle layer (27 offsets, clamped/wrapped).
// Each thread owns 4 consecutive x-cells; warp (32 threads) covers one full row.
// x-halo comes from warp shuffles; warp-edge x-neighbors are the periodic-wrap
// pairs of the reference (dist ~ 12.7 -> zero force), emulated with a 1e8 sentinel.
__device__ __forceinline__ void layer_accum(
    const float* __restrict__ px,  const float* __restrict__ py,
    const float* __restrict__ pz,  const float* __restrict__ pvx,
    const float* __restrict__ pvy, const float* __restrict__ pvz,
    int y, int z, int x0, int lane, float eta,
    const float* cx, const float* cy, const float* cz,
    const float* cvx, const float* cvy, const float* cvz,
    float* fx, float* fy, float* fz)
{
#pragma unroll 1
    for (int r = 0; r < 9; ++r) {
        int dzo = r / 3 - 1;
        int dyo = r % 3 - 1;
        int zz = (z + dzo) & (D - 1);
        int yy = (y + dyo) & (D - 1);
        int base = (zz * D + yy) * D + x0;

        float4 nx4  = ldg4(px  + base);
        float4 ny4  = ldg4(py  + base);
        float4 nz4  = ldg4(pz  + base);
        float4 nvx4 = ldg4(pvx + base);
        float4 nvy4 = ldg4(pvy + base);
        float4 nvz4 = ldg4(pvz + base);

        float wx[6], wy[6], wz[6], wvx[6], wvy[6], wvz[6];
        wx[1] = nx4.x;  wx[2] = nx4.y;  wx[3] = nx4.z;  wx[4] = nx4.w;
        wy[1] = ny4.x;  wy[2] = ny4.y;  wy[3] = ny4.z;  wy[4] = ny4.w;
        wz[1] = nz4.x;  wz[2] = nz4.y;  wz[3] = nz4.z;  wz[4] = nz4.w;
        wvx[1] = nvx4.x; wvx[2] = nvx4.y; wvx[3] = nvx4.z; wvx[4] = nvx4.w;
        wvy[1] = nvy4.x; wvy[2] = nvy4.y; wvy[3] = nvy4.z; wvy[4] = nvy4.w;
        wvz[1] = nvz4.x; wvz[2] = nvz4.y; wvz[3] = nvz4.z; wvz[4] = nvz4.w;

        wx[0]  = __shfl_up_sync(FULLMASK, nx4.w, 1);
        wy[0]  = __shfl_up_sync(FULLMASK, ny4.w, 1);
        wz[0]  = __shfl_up_sync(FULLMASK, nz4.w, 1);
        wvx[0] = __shfl_up_sync(FULLMASK, nvx4.w, 1);
        wvy[0] = __shfl_up_sync(FULLMASK, nvy4.w, 1);
        wvz[0] = __shfl_up_sync(FULLMASK, nvz4.w, 1);

        wx[5]  = __shfl_down_sync(FULLMASK, nx4.x, 1);
        wy[5]  = __shfl_down_sync(FULLMASK, ny4.x, 1);
        wz[5]  = __shfl_down_sync(FULLMASK, nz4.x, 1);
        wvx[5] = __shfl_down_sync(FULLMASK, nvx4.x, 1);
        wvy[5] = __shfl_down_sync(FULLMASK, nvy4.x, 1);
        wvz[5] = __shfl_down_sync(FULLMASK, nvz4.x, 1);

        // Periodic-wrap pairs in x: force them to zero contribution via a huge
        // position gap (dist >> PS gates coef to 0, matching the reference).
        if (lane == 0)  wx[0] = 1.0e8f;
        if (lane == 31) wx[5] = 1.0e8f;

#pragma unroll
        for (int i = 0; i < 4; ++i) {
#pragma unroll
            for (int o = 0; o < 3; ++o) {
                const int j = i + o;   // neighbor at x offset o-1
                float d_x = cx[i] - wx[j];
                float d_y = cy[i] - wy[j];
                float d_z = cz[i] - wz[j];
                float d2 = fmaf(d_x, d_x, fmaf(d_y, d_y, d_z * d_z));
                d2 = fmaxf(d2, 1e-12f);
                float rs   = rsqrtf(d2);
                float dist = d2 * rs;
                // dc = max(dist, 1e-4); r = 1/dc. When dist >= 1e-4, 1/dist == rs.
                float rinv = (dist >= 1e-4f) ? rs : 1e4f;
                float dvx = cvx[i] - wvx[j];
                float dvy = cvy[i] - wvy[j];
                float dvz = cvz[i] - wvz[j];
                float num  = fmaf(dvx, d_x, fmaf(dvy, d_y, dvz * d_z));
                float coef = fmaf(6.0e6f, dist - 0.1f, eta * (num * rinv)) * rinv;
                if (d2 < 0.01f) {   // dist < particle_size
                    fx[i] = fmaf(coef, d_x, fx[i]);
                    fy[i] = fmaf(coef, d_y, fy[i]);
                    fz[i] = fmaf(coef, d_z, fz[i]);
                }
            }
        }
    }
}

__device__ __forceinline__ float boundary_force(float p, float v, float mk, float eta) {
    float flo = (p > 0.1f && p < 0.15f) ? 1.0f : 0.0f;
    float fhi = (p > 12.65f) ? 1.0f : 0.0f;
    return 6.0e6f * flo * mk * (0.15f - p)
         - 6.0e6f * fhi * mk * (((p - 12.8f) + 0.1f) + 0.05f)
         - eta * v * flo * mk
         - eta * v * fhi * mk;
}

__global__ void __launch_bounds__(128)
dem_pass(const float* __restrict__ xg, const float* __restrict__ yg,
         const float* __restrict__ zg,
         const float* __restrict__ v0x, const float* __restrict__ v0y,
         const float* __restrict__ v0z,
         const float* __restrict__ v1x, const float* __restrict__ v1y,
         const float* __restrict__ v1z,
         const float* __restrict__ mask,
         float* __restrict__ out,
         int n, float eta, float dt_pm, float g0)
{
    const int lane = threadIdx.x;                       // 0..31, warp == one row
    const int y = blockIdx.y * 4 + threadIdx.y;         // blockDim = (32,4,1)
    const int z = blockIdx.z;
    const int x0 = lane << 2;
    const int idxc = (z * D + y) * D + x0;
    const int nofs = n * DD;

    float4 cx4 = ldg4(xg + nofs + idxc);
    float4 cy4 = ldg4(yg + nofs + idxc);
    float4 cz4 = ldg4(zg + nofs + idxc);
    const float* cvxp = n ? v1x : v0x;
    const float* cvyp = n ? v1y : v0y;
    const float* cvzp = n ? v1z : v0z;
    float4 cvx4 = ldg4(cvxp + idxc);
    float4 cvy4 = ldg4(cvyp + idxc);
    float4 cvz4 = ldg4(cvzp + idxc);

    float cx[4]  = {cx4.x,  cx4.y,  cx4.z,  cx4.w};
    float cy[4]  = {cy4.x,  cy4.y,  cy4.z,  cy4.w};
    float cz[4]  = {cz4.x,  cz4.y,  cz4.z,  cz4.w};
    float cvx[4] = {cvx4.x, cvx4.y, cvx4.z, cvx4.w};
    float cvy[4] = {cvy4.x, cvy4.y, cvy4.z, cvy4.w};
    float cvz[4] = {cvz4.x, cvz4.y, cvz4.z, cvz4.w};

    float fx[4] = {0.f, 0.f, 0.f, 0.f};
    float fy[4] = {0.f, 0.f, 0.f, 0.f};
    float fz[4] = {0.f, 0.f, 0.f, 0.f};

    // m = 0 layer, then m = 1 layer
    layer_accum(xg,      yg,      zg,      v0x, v0y, v0z,
                y, z, x0, lane, eta, cx, cy, cz, cvx, cvy, cvz, fx, fy, fz);
    layer_accum(xg + DD, yg + DD, zg + DD, v1x, v1y, v1z,
                y, z, x0, lane, eta, cx, cy, cz, cvx, cvy, cvz, fx, fy, fz);

    float4 mk4 = ldg4(mask + nofs + idxc);
    float mk[4] = {mk4.x, mk4.y, mk4.z, mk4.w};

    float ox[4], oy[4], oz[4];
#pragma unroll
    for (int i = 0; i < 4; ++i) {
        float t = dt_pm * mk[i];
        float fbx = boundary_force(cx[i], cvx[i], mk[i], eta);
        float fby = boundary_force(cy[i], cvy[i], mk[i], eta);
        float fbz = boundary_force(cz[i], cvz[i], mk[i], eta);
        ox[i] = cvx[i] + t * (fbx - fx[i]);
        oy[i] = cvy[i] + t * (fby - fy[i]);
        oz[i] = cvz[i] + t * ((g0 - fz[i]) + fbz);
    }

    *reinterpret_cast<float4*>(out + (0 * 2 + n) * DD + idxc) =
        make_float4(ox[0], ox[1], ox[2], ox[3]);
    *reinterpret_cast<float4*>(out + (1 * 2 + n) * DD + idxc) =
        make_float4(oy[0], oy[1], oy[2], oy[3]);
    *reinterpret_cast<float4*>(out + (2 * 2 + n) * DD + idxc) =
        make_float4(oz[0], oz[1], oz[2], oz[3]);
}

extern "C" void kernel_launch(void* const* d_in, const int* in_sizes, int n_in,
                              void* d_out, int out_size)
{
    const float* xg   = (const float*)d_in[0];
    const float* yg   = (const float*)d_in[1];
    const float* zg   = (const float*)d_in[2];
    const float* vx   = (const float*)d_in[3];
    const float* vy   = (const float*)d_in[4];
    const float* vz   = (const float*)d_in[5];
    const float* mask = (const float*)d_in[6];
    float* out = (float*)d_out;

    // Constants computed in double to match the python-scalar arithmetic.
    const double PM    = 4.0 / 3.0 * 3.1415 * (0.1 * 0.1 * 0.1) * 2700.0;
    const double alpha = 0.6931471805599453 / 3.141592653589793;  // -log(0.5)/pi
    const double gamma = alpha / sqrt(alpha * alpha + 1.0);
    const float eta    = (float)(2.0 * gamma * sqrt(6.0e6 * PM));
    const float dt_pm  = (float)(1e-4 / PM);
    const float g0     = (float)(-9.8 * PM);

    dim3 blk(32, 4, 1);
    dim3 grd(1, D / 4, D);

    // Pass n=0: both velocity layers come from the inputs.
    dem_pass<<<grd, blk>>>(xg, yg, zg,
                           vx, vy, vz,
                           vx + DD, vy + DD, vz + DD,
                           mask, out, 0, eta, dt_pm, g0);

    // Pass n=1: layer-0 velocities are the just-updated ones living in out.
    dem_pass<<<grd, blk>>>(xg, yg, zg,
                           out + 0 * 2 * DD, out + 1 * 2 * DD, out + 2 * 2 * DD,
                           vx + DD, vy + DD, vz + DD,
                           mask, out, 1, eta, dt_pm, g0);
}